// round 4
// baseline (speedup 1.0000x reference)
#include <cuda_runtime.h>

// Problem constants
#define TT   64
#define BB   512
#define DD   768
#define HH   12
#define HDIM 64
#define D3   2304          // 3*D
#define TB   32768         // T*B

typedef unsigned long long u64;

// Scratch (device globals — no allocation allowed)
__device__ float g_qkv[(size_t)TB * D3];   // (T,B,3D)
__device__ float g_ctx[(size_t)TB * DD];   // attention output (T,B,D)
__device__ float g_out[(size_t)TB * DD];   // after out_proj (T,B,D)
__device__ float g_mean[TT * DD];          // mean of normalized rows per t

// ---------------- packed fp32x2 helpers (Blackwell 2xFP32 path) ----------------
__device__ __forceinline__ u64 pack2(float lo, float hi) {
    u64 r; asm("mov.b64 %0, {%1, %2};" : "=l"(r) : "f"(lo), "f"(hi)); return r;
}
__device__ __forceinline__ u64 fma2(u64 a, u64 b, u64 c) {
    u64 d; asm("fma.rn.f32x2 %0, %1, %2, %3;" : "=l"(d) : "l"(a), "l"(b), "l"(c)); return d;
}
__device__ __forceinline__ u64 mul2(u64 a, u64 b) {
    u64 d; asm("mul.rn.f32x2 %0, %1, %2;" : "=l"(d) : "l"(a), "l"(b)); return d;
}
__device__ __forceinline__ float2 unpack2(u64 v) {
    float lo, hi; asm("mov.b64 {%0, %1}, %2;" : "=f"(lo), "=f"(hi) : "l"(v));
    return make_float2(lo, hi);
}

// ---------------- GEMM: C[M,N] = A[M,K] * B[N,K]^T + bias[N] ----------------
// Both operands K-contiguous (TN). 128x128x16 tiles, 256 threads, 8x8 micro-tile,
// inner product done with packed f32x2 FMA (2 fp32 FMAs per instruction).
__global__ __launch_bounds__(256)
void sgemm_tn(const float* __restrict__ A, const float* __restrict__ B,
              const float* __restrict__ bias, float* __restrict__ C,
              int M, int N, int K)
{
    __shared__ float As[16][132];
    __shared__ float Bs[16][132];

    const int tid = threadIdx.x;
    const int m0 = blockIdx.y * 128;
    const int n0 = blockIdx.x * 128;
    const int tx = tid & 15;       // 0..15  -> n micro-tile
    const int ty = tid >> 4;       // 0..15  -> m micro-tile
    const int lr = tid >> 2;       // 0..63  load row
    const int lc = (tid & 3) * 4;  // 0,4,8,12 load col (float4)

    u64 acc[8][4];
    #pragma unroll
    for (int i = 0; i < 8; i++)
        #pragma unroll
        for (int j = 0; j < 4; j++) acc[i][j] = 0ull;

    for (int k0 = 0; k0 < K; k0 += 16) {
        #pragma unroll
        for (int l = 0; l < 2; l++) {
            int row = lr + l * 64;
            float4 va = *(const float4*)&A[(size_t)(m0 + row) * K + k0 + lc];
            As[lc + 0][row] = va.x; As[lc + 1][row] = va.y;
            As[lc + 2][row] = va.z; As[lc + 3][row] = va.w;
            float4 vb = *(const float4*)&B[(size_t)(n0 + row) * K + k0 + lc];
            Bs[lc + 0][row] = vb.x; Bs[lc + 1][row] = vb.y;
            Bs[lc + 2][row] = vb.z; Bs[lc + 3][row] = vb.w;
        }
        __syncthreads();

        #pragma unroll
        for (int k = 0; k < 16; k++) {
            float4 a0 = *(const float4*)&As[k][ty * 8];
            float4 a1 = *(const float4*)&As[k][ty * 8 + 4];
            float4 bl = *(const float4*)&Bs[k][tx * 8];
            float4 bh = *(const float4*)&Bs[k][tx * 8 + 4];
            u64 b0 = pack2(bl.x, bl.y), b1 = pack2(bl.z, bl.w);
            u64 b2 = pack2(bh.x, bh.y), b3 = pack2(bh.z, bh.w);
            float av[8] = {a0.x, a0.y, a0.z, a0.w, a1.x, a1.y, a1.z, a1.w};
            #pragma unroll
            for (int i = 0; i < 8; i++) {
                u64 aa = pack2(av[i], av[i]);
                acc[i][0] = fma2(aa, b0, acc[i][0]);
                acc[i][1] = fma2(aa, b1, acc[i][1]);
                acc[i][2] = fma2(aa, b2, acc[i][2]);
                acc[i][3] = fma2(aa, b3, acc[i][3]);
            }
        }
        __syncthreads();
    }

    const int n = n0 + tx * 8;
    float4 bias_l = *(const float4*)&bias[n];
    float4 bias_h = *(const float4*)&bias[n + 4];
    #pragma unroll
    for (int i = 0; i < 8; i++) {
        int m = m0 + ty * 8 + i;
        float2 v0 = unpack2(acc[i][0]), v1 = unpack2(acc[i][1]);
        float2 v2 = unpack2(acc[i][2]), v3 = unpack2(acc[i][3]);
        float4 o0 = make_float4(v0.x + bias_l.x, v0.y + bias_l.y,
                                v1.x + bias_l.z, v1.y + bias_l.w);
        float4 o1 = make_float4(v2.x + bias_h.x, v2.y + bias_h.y,
                                v3.x + bias_h.z, v3.y + bias_h.w);
        *(float4*)&C[(size_t)m * N + n]     = o0;
        *(float4*)&C[(size_t)m * N + n + 4] = o1;
    }
}

// ---------------- Attention: per (t, h, 64-query tile), online softmax ----------------
// 64 threads per block, one query row per thread. Q scaled by 1/sqrt(HD) up front.
__global__ __launch_bounds__(64)
void attn_kernel()
{
    __shared__ float Ks[64][68];
    __shared__ float Vs[64][68];

    const int bid = blockIdx.x;
    const int qt  = bid & 7;
    const int h   = (bid >> 3) % HH;
    const int t   = bid / (8 * HH);
    const int tid = threadIdx.x;
    const int bq  = qt * 64 + tid;

    const size_t rowbase = (size_t)(t * BB) * D3;
    const float* __restrict__ qptr = &g_qkv[rowbase + (size_t)bq * D3 + h * HDIM];

    u64 qp[32];
    #pragma unroll
    for (int i = 0; i < 32; i++) qp[i] = *(const u64*)(qptr + 2 * i);
    const u64 sc = pack2(0.125f, 0.125f);    // 1/sqrt(64)
    #pragma unroll
    for (int i = 0; i < 32; i++) qp[i] = mul2(qp[i], sc);

    u64 accp[32];
    #pragma unroll
    for (int i = 0; i < 32; i++) accp[i] = 0ull;
    float m = -3.402823466e38f;
    float l = 0.f;

    #pragma unroll 1
    for (int c0 = 0; c0 < BB; c0 += 64) {
        const float* kr = &g_qkv[rowbase + (size_t)(c0 + tid) * D3 + DD + h * HDIM];
        const float* vr = kr + DD;
        #pragma unroll
        for (int i = 0; i < 16; i++) {
            *(float4*)&Ks[tid][4 * i] = *(const float4*)(kr + 4 * i);
            *(float4*)&Vs[tid][4 * i] = *(const float4*)(vr + 4 * i);
        }
        __syncthreads();

        #pragma unroll 1
        for (int j = 0; j < 64; j++) {
            const ulonglong2* kp = (const ulonglong2*)&Ks[j][0];
            u64 s0 = 0ull, s1 = 0ull, s2 = 0ull, s3 = 0ull;
            #pragma unroll
            for (int d = 0; d < 16; d += 2) {
                ulonglong2 k0v = kp[d];
                ulonglong2 k1v = kp[d + 1];
                s0 = fma2(qp[2 * d],     k0v.x, s0);
                s1 = fma2(qp[2 * d + 1], k0v.y, s1);
                s2 = fma2(qp[2 * d + 2], k1v.x, s2);
                s3 = fma2(qp[2 * d + 3], k1v.y, s3);
            }
            float2 f0 = unpack2(s0), f1 = unpack2(s1);
            float2 f2 = unpack2(s2), f3 = unpack2(s3);
            float s = ((f0.x + f0.y) + (f1.x + f1.y)) +
                      ((f2.x + f2.y) + (f3.x + f3.y));

            if (s > m) {                      // rare after warmup
                float corr = __expf(m - s);   // first iter: exp(-inf)=0, acc already 0
                m = s;
                l *= corr;
                u64 cp = pack2(corr, corr);
                #pragma unroll
                for (int d = 0; d < 32; d++) accp[d] = mul2(accp[d], cp);
            }
            float p = __expf(s - m);
            l += p;
            u64 pp = pack2(p, p);
            const ulonglong2* vp = (const ulonglong2*)&Vs[j][0];
            #pragma unroll
            for (int d = 0; d < 16; d++) {
                ulonglong2 vv = vp[d];
                accp[2 * d]     = fma2(pp, vv.x, accp[2 * d]);
                accp[2 * d + 1] = fma2(pp, vv.y, accp[2 * d + 1]);
            }
        }
        __syncthreads();
    }

    float invl = 1.f / l;
    u64 ip = pack2(invl, invl);
    float* op = &g_ctx[(size_t)(t * BB + bq) * DD + h * HDIM];
    #pragma unroll
    for (int d = 0; d < 32; d++) {
        *(u64*)(op + 2 * d) = mul2(accp[d], ip);
    }
}

// ---------------- mean of normalized rows per t ----------------
// adj[t,j] = (mean_i out_i/||out_i||) . out_j/||out_j||  (sim matrix eliminated)
__global__ __launch_bounds__(256)
void mean_kernel()
{
    const int t    = blockIdx.x;
    const int warp = threadIdx.x >> 5;
    const int lane = threadIdx.x & 31;

    float macc[24];
    #pragma unroll
    for (int k = 0; k < 24; k++) macc[k] = 0.f;

    for (int b = warp; b < BB; b += 8) {
        const float* row = &g_out[(size_t)(t * BB + b) * DD];
        float x[24];
        float ss = 0.f;
        #pragma unroll
        for (int k = 0; k < 24; k++) {
            x[k] = row[lane + 32 * k];
            ss += x[k] * x[k];
        }
        #pragma unroll
        for (int o = 16; o; o >>= 1) ss += __shfl_xor_sync(0xffffffffu, ss, o);
        float r = 1.f / fmaxf(sqrtf(ss), 1e-8f);
        #pragma unroll
        for (int k = 0; k < 24; k++) macc[k] += x[k] * r;
    }

    __shared__ float sm[8][DD];
    #pragma unroll
    for (int k = 0; k < 24; k++) sm[warp][lane + 32 * k] = macc[k];
    __syncthreads();

    for (int d = threadIdx.x; d < DD; d += 256) {
        float s = 0.f;
        #pragma unroll
        for (int w = 0; w < 8; w++) s += sm[w][d];
        g_mean[t * DD + d] = s * (1.f / (float)BB);
    }
}

// ---------------- adjacency: one warp per (t,b) row ----------------
__global__ __launch_bounds__(256)
void adj_kernel(float* __restrict__ adj)
{
    const int row  = blockIdx.x * 8 + (threadIdx.x >> 5);
    const int lane = threadIdx.x & 31;
    const int t    = row >> 9;   // /512

    const float* __restrict__ x = &g_out[(size_t)row * DD];
    const float* __restrict__ mv = &g_mean[t * DD];

    float dot = 0.f, ss = 0.f;
    #pragma unroll
    for (int k = 0; k < 24; k++) {
        float v = x[lane + 32 * k];
        dot += v * mv[lane + 32 * k];
        ss  += v * v;
    }
    #pragma unroll
    for (int o = 16; o; o >>= 1) {
        dot += __shfl_xor_sync(0xffffffffu, dot, o);
        ss  += __shfl_xor_sync(0xffffffffu, ss, o);
    }
    if (lane == 0)
        adj[row] = dot / fmaxf(sqrtf(ss), 1e-8f);
}

// ---------------- launch ----------------
static const float* find_by_count(void* const* d_in, const int* in_sizes,
                                  int n_in, int count)
{
    for (int i = 0; i < n_in; i++)
        if (in_sizes[i] == count) return (const float*)d_in[i];
    return nullptr;
}

extern "C" void kernel_launch(void* const* d_in, const int* in_sizes, int n_in,
                              void* d_out, int out_size)
{
    // robust mapping by element count (all five are distinct)
    const float* node  = find_by_count(d_in, in_sizes, n_in, TB * DD);      // 25165824
    const float* w_in  = find_by_count(d_in, in_sizes, n_in, D3 * DD);      // 1769472
    const float* b_in  = find_by_count(d_in, in_sizes, n_in, D3);           // 2304
    const float* w_out = find_by_count(d_in, in_sizes, n_in, DD * DD);      // 589824
    const float* b_out = find_by_count(d_in, in_sizes, n_in, DD);           // 768
    float* adj = (float*)d_out;

    float *qkv_p, *ctx_p, *out_p;
    cudaGetSymbolAddress((void**)&qkv_p, g_qkv);
    cudaGetSymbolAddress((void**)&ctx_p, g_ctx);
    cudaGetSymbolAddress((void**)&out_p, g_out);

    // 1) QKV projection: (32768 x 768) x (2304 x 768)^T
    sgemm_tn<<<dim3(D3 / 128, TB / 128), 256>>>(node, w_in, b_in, qkv_p, TB, D3, DD);
    // 2) attention over B per (t, h)
    attn_kernel<<<TT * HH * 8, 64>>>();
    // 3) out projection: (32768 x 768) x (768 x 768)^T
    sgemm_tn<<<dim3(DD / 128, TB / 128), 256>>>(ctx_p, w_out, b_out, out_p, TB, DD, DD);
    // 4) per-t mean of normalized rows
    mean_kernel<<<TT, 256>>>();
    // 5) adjacency output (T*B floats)
    adj_kernel<<<TB / 8, 256>>>(adj);
}

// round 10
// speedup vs baseline: 1.5128x; 1.5128x over previous
#include <cuda_runtime.h>
#include <cuda_bf16.h>

// Problem constants
#define TT   64
#define BB   512
#define DD   768
#define HH   12
#define HDIM 64
#define D3   2304
#define TB   32768
#define KDIM 768
#define NCH  24                 // K chunks of 32

typedef unsigned long long u64;
typedef unsigned int u32;

// ---------------- device globals (no allocation allowed) ----------------
__device__ float g_qkv[(size_t)TB * D3];
__device__ float g_ctx[(size_t)TB * DD];
__device__ float g_out[(size_t)TB * DD];
__device__ float g_mean[TT * DD];
__device__ __nv_bfloat16 g_Ah[(size_t)TB * DD];   // activation hi (reused gemm1/gemm2)
__device__ __nv_bfloat16 g_Al[(size_t)TB * DD];   // activation lo
__device__ __nv_bfloat16 g_Wh[(size_t)D3 * DD];   // weight hi (reused)
__device__ __nv_bfloat16 g_Wl[(size_t)D3 * DD];   // weight lo

// ---------------- packed fp32x2 helpers ----------------
__device__ __forceinline__ u64 pack2(float lo, float hi) {
    u64 r; asm("mov.b64 %0, {%1, %2};" : "=l"(r) : "f"(lo), "f"(hi)); return r;
}
__device__ __forceinline__ u64 fma2(u64 a, u64 b, u64 c) {
    u64 d; asm("fma.rn.f32x2 %0, %1, %2, %3;" : "=l"(d) : "l"(a), "l"(b), "l"(c)); return d;
}
__device__ __forceinline__ u64 mul2(u64 a, u64 b) {
    u64 d; asm("mul.rn.f32x2 %0, %1, %2;" : "=l"(d) : "l"(a), "l"(b)); return d;
}
__device__ __forceinline__ float2 unpack2(u64 v) {
    float lo, hi; asm("mov.b64 {%0, %1}, %2;" : "=f"(lo), "=f"(hi) : "l"(v));
    return make_float2(lo, hi);
}

// ---------------- portable tensor-core helpers (sm_80-era PTX, ok on sm_103) ----------------
__device__ __forceinline__ u32 smem_u32(const void* p) {
    u32 a;
    asm("{ .reg .u64 t; cvta.to.shared.u64 t, %1; cvt.u32.u64 %0, t; }" : "=r"(a) : "l"(p));
    return a;
}
__device__ __forceinline__ void cp16(u32 dst, const void* src) {
    asm volatile("cp.async.cg.shared.global [%0], [%1], 16;" :: "r"(dst), "l"(src) : "memory");
}
__device__ __forceinline__ void ldmx4(u32* r, u32 addr) {
    asm volatile("ldmatrix.sync.aligned.m8n8.x4.shared.b16 {%0,%1,%2,%3}, [%4];"
                 : "=r"(r[0]), "=r"(r[1]), "=r"(r[2]), "=r"(r[3]) : "r"(addr));
}
__device__ __forceinline__ void mma_bf16(float* c, const u32* a, const u32* b) {
    asm volatile("mma.sync.aligned.m16n8k16.row.col.f32.bf16.bf16.f32 "
                 "{%0,%1,%2,%3}, {%4,%5,%6,%7}, {%8,%9}, {%0,%1,%2,%3};"
                 : "+f"(c[0]), "+f"(c[1]), "+f"(c[2]), "+f"(c[3])
                 : "r"(a[0]), "r"(a[1]), "r"(a[2]), "r"(a[3]), "r"(b[0]), "r"(b[1]));
}

// ---------------- split-precision conversion: fp32 -> bf16 hi + bf16 lo ----------------
__global__ __launch_bounds__(256)
void split4(const float* __restrict__ x, __nv_bfloat16* __restrict__ hi,
            __nv_bfloat16* __restrict__ lo, int n4)
{
    int i = blockIdx.x * 256 + threadIdx.x;
    if (i >= n4) return;
    float4 v = ((const float4*)x)[i];
    __nv_bfloat162 h01 = __floats2bfloat162_rn(v.x, v.y);
    __nv_bfloat162 h23 = __floats2bfloat162_rn(v.z, v.w);
    float r0 = v.x - __low2float(h01);
    float r1 = v.y - __high2float(h01);
    float r2 = v.z - __low2float(h23);
    float r3 = v.w - __high2float(h23);
    __nv_bfloat162 l01 = __floats2bfloat162_rn(r0, r1);
    __nv_bfloat162 l23 = __floats2bfloat162_rn(r2, r3);
    ((__nv_bfloat162*)hi)[2 * i]     = h01;
    ((__nv_bfloat162*)hi)[2 * i + 1] = h23;
    ((__nv_bfloat162*)lo)[2 * i]     = l01;
    ((__nv_bfloat162*)lo)[2 * i + 1] = l23;
}

// ---------------- HMMA GEMM: C[M,Nld] = A[M,768] * B[N,768]^T + bias ----------------
// 3-term emulated fp32: acc += Ah*Bh + Ah*Bl + Al*Bh (fp32 accumulators).
// 128x128 tile / 256 threads; warp grid 2(M)x4(N), warp tile 64x32 = 4x4 m16n8k16.
// K chunks of 32, cp.async double-buffered. Smem rows padded to 80B so every
// ldmatrix.x4 phase covers 8 distinct 16B segments (conflict-free).
#define ROWB      80                         // padded row bytes (32 bf16 data + 16B pad)
#define PART_SZ   (128 * ROWB)               // 10240
#define BUF_SZ    (4 * PART_SZ)              // Ah,Al,Bh,Bl = 40960
#define GEMM_SMEM (512 + 2 * BUF_SZ)         // bias + double buffer = 82432

__device__ __forceinline__ void issue_chunk(u32 dst,
    const __nv_bfloat16* __restrict__ Ah, const __nv_bfloat16* __restrict__ Al,
    const __nv_bfloat16* __restrict__ Bh, const __nv_bfloat16* __restrict__ Bl,
    int m0, int n0, int kc, int tid)
{
    #pragma unroll
    for (int i = 0; i < 2; i++) {
        int s = tid * 2 + i;                 // 512 slots of 16B per part
        int row = s >> 2, cc = s & 3;
        u32 soff = (u32)(row * ROWB + cc * 16);
        size_t goA = (size_t)(m0 + row) * KDIM + kc * 32 + cc * 8;
        size_t goB = (size_t)(n0 + row) * KDIM + kc * 32 + cc * 8;
        cp16(dst + soff,               Ah + goA);
        cp16(dst + PART_SZ + soff,     Al + goA);
        cp16(dst + 2 * PART_SZ + soff, Bh + goB);
        cp16(dst + 3 * PART_SZ + soff, Bl + goB);
    }
}

__global__ __launch_bounds__(256)
void hgemm(const __nv_bfloat16* __restrict__ Ah, const __nv_bfloat16* __restrict__ Al,
           const __nv_bfloat16* __restrict__ Bh, const __nv_bfloat16* __restrict__ Bl,
           const float* __restrict__ bias, float* __restrict__ C, int Nld)
{
    extern __shared__ char smem[];
    const u32 sbase = smem_u32(smem);
    const int tid  = threadIdx.x;
    const int lane = tid & 31, wid = tid >> 5;
    const int wm = wid & 1, wn = wid >> 1;           // 2 x 4 warp grid
    const int m0 = blockIdx.y * 128, n0 = blockIdx.x * 128;

    float* bs = (float*)smem;
    if (tid < 128) bs[tid] = bias[n0 + tid];

    // ldmatrix per-lane address offsets (within a part, at tile origin)
    const u32 laneA = (u32)((lane & 15) * ROWB + (lane >> 4) * 16);
    const u32 laneB = (u32)(((((lane >> 4) << 3) + (lane & 7)) * ROWB) + ((lane >> 3) & 1) * 16);

    float acc[4][4][4];
    #pragma unroll
    for (int mi = 0; mi < 4; mi++)
        #pragma unroll
        for (int ni = 0; ni < 4; ni++)
            #pragma unroll
            for (int j = 0; j < 4; j++) acc[mi][ni][j] = 0.f;

    const u32 bufs = sbase + 512;

    issue_chunk(bufs,          Ah, Al, Bh, Bl, m0, n0, 0, tid);
    asm volatile("cp.async.commit_group;" ::: "memory");
    issue_chunk(bufs + BUF_SZ, Ah, Al, Bh, Bl, m0, n0, 1, tid);
    asm volatile("cp.async.commit_group;" ::: "memory");

    #pragma unroll 1
    for (int c = 0; c < NCH; c++) {
        if (c + 2 < NCH) asm volatile("cp.async.wait_group 1;" ::: "memory");
        else             asm volatile("cp.async.wait_group 0;" ::: "memory");
        __syncthreads();

        const u32 buf = bufs + (u32)(c & 1) * BUF_SZ;
        #pragma unroll
        for (int kk = 0; kk < 2; kk++) {               // two k16 steps per chunk
            const u32 koff = (u32)(kk * 32);
            const u32 aH = buf + (u32)(wm * 64 * ROWB) + koff + laneA;
            const u32 bH = buf + 2 * PART_SZ + (u32)(wn * 32 * ROWB) + koff + laneB;
            u32 ah[4][4], al[4][4], bh[2][4], bl[2][4];
            #pragma unroll
            for (int mi = 0; mi < 4; mi++) {
                ldmx4(ah[mi], aH + (u32)(mi * 16 * ROWB));
                ldmx4(al[mi], aH + PART_SZ + (u32)(mi * 16 * ROWB));
            }
            #pragma unroll
            for (int nb = 0; nb < 2; nb++) {
                ldmx4(bh[nb], bH + (u32)(nb * 16 * ROWB));
                ldmx4(bl[nb], bH + PART_SZ + (u32)(nb * 16 * ROWB));
            }
            #pragma unroll
            for (int mi = 0; mi < 4; mi++)
                #pragma unroll
                for (int ni = 0; ni < 4; ni++) {
                    const u32* bhp = &bh[ni >> 1][(ni & 1) * 2];
                    const u32* blp = &bl[ni >> 1][(ni & 1) * 2];
                    mma_bf16(acc[mi][ni], ah[mi], bhp);
                    mma_bf16(acc[mi][ni], ah[mi], blp);
                    mma_bf16(acc[mi][ni], al[mi], bhp);
                }
        }
        __syncthreads();
        if (c + 2 < NCH) {
            issue_chunk(bufs + (u32)(c & 1) * BUF_SZ, Ah, Al, Bh, Bl, m0, n0, c + 2, tid);
            asm volatile("cp.async.commit_group;" ::: "memory");
        }
    }

    // epilogue: fragment -> gmem with bias
    const int g = lane >> 2, tq = lane & 3;
    #pragma unroll
    for (int mi = 0; mi < 4; mi++) {
        #pragma unroll
        for (int ni = 0; ni < 4; ni++) {
            int row = m0 + wm * 64 + mi * 16 + g;
            int nl  = wn * 32 + ni * 8 + 2 * tq;
            float b0v = bs[nl], b1v = bs[nl + 1];
            float2 v0 = make_float2(acc[mi][ni][0] + b0v, acc[mi][ni][1] + b1v);
            float2 v1 = make_float2(acc[mi][ni][2] + b0v, acc[mi][ni][3] + b1v);
            *(float2*)&C[(size_t)row * Nld + n0 + nl]       = v0;
            *(float2*)&C[(size_t)(row + 8) * Nld + n0 + nl] = v1;
        }
    }
}

// ---------------- Attention: per (t, h, 64-query tile), online softmax ----------------
__global__ __launch_bounds__(64)
void attn_kernel()
{
    __shared__ float Ks[64][68];
    __shared__ float Vs[64][68];

    const int bid = blockIdx.x;
    const int qt  = bid & 7;
    const int h   = (bid >> 3) % HH;
    const int t   = bid / (8 * HH);
    const int tid = threadIdx.x;
    const int bq  = qt * 64 + tid;

    const size_t rowbase = (size_t)(t * BB) * D3;
    const float* __restrict__ qptr = &g_qkv[rowbase + (size_t)bq * D3 + h * HDIM];

    u64 qp[32];
    #pragma unroll
    for (int i = 0; i < 32; i++) qp[i] = *(const u64*)(qptr + 2 * i);
    const u64 sc = pack2(0.125f, 0.125f);
    #pragma unroll
    for (int i = 0; i < 32; i++) qp[i] = mul2(qp[i], sc);

    u64 accp[32];
    #pragma unroll
    for (int i = 0; i < 32; i++) accp[i] = 0ull;
    float m = -3.402823466e38f;
    float l = 0.f;

    #pragma unroll 1
    for (int c0 = 0; c0 < BB; c0 += 64) {
        const float* kr = &g_qkv[rowbase + (size_t)(c0 + tid) * D3 + DD + h * HDIM];
        const float* vr = kr + DD;
        #pragma unroll
        for (int i = 0; i < 16; i++) {
            *(float4*)&Ks[tid][4 * i] = *(const float4*)(kr + 4 * i);
            *(float4*)&Vs[tid][4 * i] = *(const float4*)(vr + 4 * i);
        }
        __syncthreads();

        #pragma unroll 1
        for (int j = 0; j < 64; j++) {
            const ulonglong2* kp = (const ulonglong2*)&Ks[j][0];
            u64 s0 = 0ull, s1 = 0ull, s2 = 0ull, s3 = 0ull;
            #pragma unroll
            for (int d = 0; d < 16; d += 2) {
                ulonglong2 k0v = kp[d];
                ulonglong2 k1v = kp[d + 1];
                s0 = fma2(qp[2 * d],     k0v.x, s0);
                s1 = fma2(qp[2 * d + 1], k0v.y, s1);
                s2 = fma2(qp[2 * d + 2], k1v.x, s2);
                s3 = fma2(qp[2 * d + 3], k1v.y, s3);
            }
            float2 f0 = unpack2(s0), f1 = unpack2(s1);
            float2 f2 = unpack2(s2), f3 = unpack2(s3);
            float s = ((f0.x + f0.y) + (f1.x + f1.y)) +
                      ((f2.x + f2.y) + (f3.x + f3.y));

            if (s > m) {
                float corr = __expf(m - s);
                m = s;
                l *= corr;
                u64 cp = pack2(corr, corr);
                #pragma unroll
                for (int d = 0; d < 32; d++) accp[d] = mul2(accp[d], cp);
            }
            float p = __expf(s - m);
            l += p;
            u64 pp = pack2(p, p);
            const ulonglong2* vp = (const ulonglong2*)&Vs[j][0];
            #pragma unroll
            for (int d = 0; d < 16; d++) {
                ulonglong2 vv = vp[d];
                accp[2 * d]     = fma2(pp, vv.x, accp[2 * d]);
                accp[2 * d + 1] = fma2(pp, vv.y, accp[2 * d + 1]);
            }
        }
        __syncthreads();
    }

    float invl = 1.f / l;
    u64 ip = pack2(invl, invl);
    float* op = &g_ctx[(size_t)(t * BB + bq) * DD + h * HDIM];
    #pragma unroll
    for (int d = 0; d < 32; d++) {
        *(u64*)(op + 2 * d) = mul2(accp[d], ip);
    }
}

// ---------------- mean of normalized rows per t ----------------
__global__ __launch_bounds__(256)
void mean_kernel()
{
    const int t    = blockIdx.x;
    const int warp = threadIdx.x >> 5;
    const int lane = threadIdx.x & 31;

    float macc[24];
    #pragma unroll
    for (int k = 0; k < 24; k++) macc[k] = 0.f;

    for (int b = warp; b < BB; b += 8) {
        const float* row = &g_out[(size_t)(t * BB + b) * DD];
        float x[24];
        float ss = 0.f;
        #pragma unroll
        for (int k = 0; k < 24; k++) {
            x[k] = row[lane + 32 * k];
            ss += x[k] * x[k];
        }
        #pragma unroll
        for (int o = 16; o; o >>= 1) ss += __shfl_xor_sync(0xffffffffu, ss, o);
        float r = 1.f / fmaxf(sqrtf(ss), 1e-8f);
        #pragma unroll
        for (int k = 0; k < 24; k++) macc[k] += x[k] * r;
    }

    __shared__ float sm[8][DD];
    #pragma unroll
    for (int k = 0; k < 24; k++) sm[warp][lane + 32 * k] = macc[k];
    __syncthreads();

    for (int d = threadIdx.x; d < DD; d += 256) {
        float s = 0.f;
        #pragma unroll
        for (int w = 0; w < 8; w++) s += sm[w][d];
        g_mean[t * DD + d] = s * (1.f / (float)BB);
    }
}

// ---------------- adjacency: one warp per (t,b) row ----------------
__global__ __launch_bounds__(256)
void adj_kernel(float* __restrict__ adj)
{
    const int row  = blockIdx.x * 8 + (threadIdx.x >> 5);
    const int lane = threadIdx.x & 31;
    const int t    = row >> 9;

    const float* __restrict__ x = &g_out[(size_t)row * DD];
    const float* __restrict__ mv = &g_mean[t * DD];

    float dot = 0.f, ss = 0.f;
    #pragma unroll
    for (int k = 0; k < 24; k++) {
        float v = x[lane + 32 * k];
        dot += v * mv[lane + 32 * k];
        ss  += v * v;
    }
    #pragma unroll
    for (int o = 16; o; o >>= 1) {
        dot += __shfl_xor_sync(0xffffffffu, dot, o);
        ss  += __shfl_xor_sync(0xffffffffu, ss, o);
    }
    if (lane == 0)
        adj[row] = dot / fmaxf(sqrtf(ss), 1e-8f);
}

// ---------------- launch ----------------
static const float* find_by_count(void* const* d_in, const int* in_sizes,
                                  int n_in, int count)
{
    for (int i = 0; i < n_in; i++)
        if (in_sizes[i] == count) return (const float*)d_in[i];
    return nullptr;
}

extern "C" void kernel_launch(void* const* d_in, const int* in_sizes, int n_in,
                              void* d_out, int out_size)
{
    const float* node  = find_by_count(d_in, in_sizes, n_in, TB * DD);
    const float* w_in  = find_by_count(d_in, in_sizes, n_in, D3 * DD);
    const float* b_in  = find_by_count(d_in, in_sizes, n_in, D3);
    const float* w_out = find_by_count(d_in, in_sizes, n_in, DD * DD);
    const float* b_out = find_by_count(d_in, in_sizes, n_in, DD);
    float* adj = (float*)d_out;

    float *qkv_p, *ctx_p, *out_p;
    __nv_bfloat16 *ah_p, *al_p, *wh_p, *wl_p;
    cudaGetSymbolAddress((void**)&qkv_p, g_qkv);
    cudaGetSymbolAddress((void**)&ctx_p, g_ctx);
    cudaGetSymbolAddress((void**)&out_p, g_out);
    cudaGetSymbolAddress((void**)&ah_p, g_Ah);
    cudaGetSymbolAddress((void**)&al_p, g_Al);
    cudaGetSymbolAddress((void**)&wh_p, g_Wh);
    cudaGetSymbolAddress((void**)&wl_p, g_Wl);

    cudaFuncSetAttribute(hgemm, cudaFuncAttributeMaxDynamicSharedMemorySize, GEMM_SMEM);

    // 1) split node_embs and in_proj weights to bf16 hi/lo
    {
        int n4 = TB * DD / 4;
        split4<<<(n4 + 255) / 256, 256>>>(node, ah_p, al_p, n4);
        int w4 = D3 * DD / 4;
        split4<<<(w4 + 255) / 256, 256>>>(w_in, wh_p, wl_p, w4);
    }
    // 2) QKV projection (HMMA, emulated fp32): (32768 x 768) x (2304 x 768)^T
    hgemm<<<dim3(D3 / 128, TB / 128), 256, GEMM_SMEM>>>(ah_p, al_p, wh_p, wl_p, b_in, qkv_p, D3);
    // 3) attention over B per (t, h)
    attn_kernel<<<TT * HH * 8, 64>>>();
    // 4) split ctx + out_proj weights
    {
        int n4 = TB * DD / 4;
        split4<<<(n4 + 255) / 256, 256>>>(ctx_p, ah_p, al_p, n4);
        int w4 = DD * DD / 4;
        split4<<<(w4 + 255) / 256, 256>>>(w_out, wh_p, wl_p, w4);
    }
    // 5) out projection: (32768 x 768) x (768 x 768)^T
    hgemm<<<dim3(DD / 128, TB / 128), 256, GEMM_SMEM>>>(ah_p, al_p, wh_p, wl_p, b_out, out_p, DD);
    // 6) per-t mean of normalized rows
    mean_kernel<<<TT, 256>>>();
    // 7) adjacency output (T*B floats)
    adj_kernel<<<TB / 8, 256>>>(adj);
}

// round 12
// speedup vs baseline: 2.5761x; 1.7028x over previous
#include <cuda_runtime.h>
#include <cuda_bf16.h>

// Problem constants
#define TT   64
#define BB   512
#define DD   768
#define HH   12
#define HDIM 64
#define D3   2304
#define TB   32768
#define KDIM 768
#define NCH  24                 // GEMM K chunks of 32

typedef unsigned long long u64;
typedef unsigned int u32;

// ---------------- device globals (no allocation allowed) ----------------
__device__ float g_qkv[(size_t)TB * D3];
__device__ float g_out[(size_t)TB * DD];
__device__ float g_mean[TT * DD];
__device__ __nv_bfloat16 g_Ah[(size_t)TB * DD];   // activation hi (node, then ctx)
__device__ __nv_bfloat16 g_Al[(size_t)TB * DD];   // activation lo
__device__ __nv_bfloat16 g_Wh[(size_t)D3 * DD];   // weight hi (reused)
__device__ __nv_bfloat16 g_Wl[(size_t)D3 * DD];   // weight lo

// ---------------- portable tensor-core helpers ----------------
__device__ __forceinline__ u32 smem_u32(const void* p) {
    u32 a;
    asm("{ .reg .u64 t; cvta.to.shared.u64 t, %1; cvt.u32.u64 %0, t; }" : "=r"(a) : "l"(p));
    return a;
}
__device__ __forceinline__ void cp16(u32 dst, const void* src) {
    asm volatile("cp.async.cg.shared.global [%0], [%1], 16;" :: "r"(dst), "l"(src) : "memory");
}
__device__ __forceinline__ void ldmx4(u32* r, u32 addr) {
    asm volatile("ldmatrix.sync.aligned.m8n8.x4.shared.b16 {%0,%1,%2,%3}, [%4];"
                 : "=r"(r[0]), "=r"(r[1]), "=r"(r[2]), "=r"(r[3]) : "r"(addr));
}
__device__ __forceinline__ void mma_bf16(float* c, const u32* a, const u32* b) {
    asm volatile("mma.sync.aligned.m16n8k16.row.col.f32.bf16.bf16.f32 "
                 "{%0,%1,%2,%3}, {%4,%5,%6,%7}, {%8,%9}, {%0,%1,%2,%3};"
                 : "+f"(c[0]), "+f"(c[1]), "+f"(c[2]), "+f"(c[3])
                 : "r"(a[0]), "r"(a[1]), "r"(a[2]), "r"(a[3]), "r"(b[0]), "r"(b[1]));
}
__device__ __forceinline__ u32 b2u(__nv_bfloat16 lo, __nv_bfloat16 hi) {
    __nv_bfloat162 t(lo, hi);               // .x = low half
    return *(u32*)&t;
}

// ---------------- split-precision conversion: fp32 -> bf16 hi + bf16 lo ----------------
__global__ __launch_bounds__(256)
void split4(const float* __restrict__ x, __nv_bfloat16* __restrict__ hi,
            __nv_bfloat16* __restrict__ lo, int n4)
{
    int i = blockIdx.x * 256 + threadIdx.x;
    if (i >= n4) return;
    float4 v = ((const float4*)x)[i];
    __nv_bfloat162 h01 = __floats2bfloat162_rn(v.x, v.y);
    __nv_bfloat162 h23 = __floats2bfloat162_rn(v.z, v.w);
    float r0 = v.x - __low2float(h01);
    float r1 = v.y - __high2float(h01);
    float r2 = v.z - __low2float(h23);
    float r3 = v.w - __high2float(h23);
    __nv_bfloat162 l01 = __floats2bfloat162_rn(r0, r1);
    __nv_bfloat162 l23 = __floats2bfloat162_rn(r2, r3);
    ((__nv_bfloat162*)hi)[2 * i]     = h01;
    ((__nv_bfloat162*)hi)[2 * i + 1] = h23;
    ((__nv_bfloat162*)lo)[2 * i]     = l01;
    ((__nv_bfloat162*)lo)[2 * i + 1] = l23;
}

// ---------------- HMMA GEMM: C[M,Nld] = A[M,768] * B[N,768]^T + bias ----------------
#define ROWB      80
#define PART_SZ   (128 * ROWB)
#define BUF_SZ    (4 * PART_SZ)
#define GEMM_SMEM (512 + 2 * BUF_SZ)

__device__ __forceinline__ void issue_chunk(u32 dst,
    const __nv_bfloat16* __restrict__ Ah, const __nv_bfloat16* __restrict__ Al,
    const __nv_bfloat16* __restrict__ Bh, const __nv_bfloat16* __restrict__ Bl,
    int m0, int n0, int kc, int tid)
{
    #pragma unroll
    for (int i = 0; i < 2; i++) {
        int s = tid * 2 + i;
        int row = s >> 2, cc = s & 3;
        u32 soff = (u32)(row * ROWB + cc * 16);
        size_t goA = (size_t)(m0 + row) * KDIM + kc * 32 + cc * 8;
        size_t goB = (size_t)(n0 + row) * KDIM + kc * 32 + cc * 8;
        cp16(dst + soff,               Ah + goA);
        cp16(dst + PART_SZ + soff,     Al + goA);
        cp16(dst + 2 * PART_SZ + soff, Bh + goB);
        cp16(dst + 3 * PART_SZ + soff, Bl + goB);
    }
}

__global__ __launch_bounds__(256)
void hgemm(const __nv_bfloat16* __restrict__ Ah, const __nv_bfloat16* __restrict__ Al,
           const __nv_bfloat16* __restrict__ Bh, const __nv_bfloat16* __restrict__ Bl,
           const float* __restrict__ bias, float* __restrict__ C, int Nld)
{
    extern __shared__ char smem[];
    const u32 sbase = smem_u32(smem);
    const int tid  = threadIdx.x;
    const int lane = tid & 31, wid = tid >> 5;
    const int wm = wid & 1, wn = wid >> 1;
    const int m0 = blockIdx.y * 128, n0 = blockIdx.x * 128;

    float* bs = (float*)smem;
    if (tid < 128) bs[tid] = bias[n0 + tid];

    const u32 laneA = (u32)((lane & 15) * ROWB + (lane >> 4) * 16);
    const u32 laneB = (u32)(((((lane >> 4) << 3) + (lane & 7)) * ROWB) + ((lane >> 3) & 1) * 16);

    float acc[4][4][4];
    #pragma unroll
    for (int mi = 0; mi < 4; mi++)
        #pragma unroll
        for (int ni = 0; ni < 4; ni++)
            #pragma unroll
            for (int j = 0; j < 4; j++) acc[mi][ni][j] = 0.f;

    const u32 bufs = sbase + 512;

    issue_chunk(bufs,          Ah, Al, Bh, Bl, m0, n0, 0, tid);
    asm volatile("cp.async.commit_group;" ::: "memory");
    issue_chunk(bufs + BUF_SZ, Ah, Al, Bh, Bl, m0, n0, 1, tid);
    asm volatile("cp.async.commit_group;" ::: "memory");

    #pragma unroll 1
    for (int c = 0; c < NCH; c++) {
        if (c + 2 < NCH) asm volatile("cp.async.wait_group 1;" ::: "memory");
        else             asm volatile("cp.async.wait_group 0;" ::: "memory");
        __syncthreads();

        const u32 buf = bufs + (u32)(c & 1) * BUF_SZ;
        #pragma unroll
        for (int kk = 0; kk < 2; kk++) {
            const u32 koff = (u32)(kk * 32);
            const u32 aH = buf + (u32)(wm * 64 * ROWB) + koff + laneA;
            const u32 bH = buf + 2 * PART_SZ + (u32)(wn * 32 * ROWB) + koff + laneB;
            u32 ah[4][4], al[4][4], bh[2][4], bl[2][4];
            #pragma unroll
            for (int mi = 0; mi < 4; mi++) {
                ldmx4(ah[mi], aH + (u32)(mi * 16 * ROWB));
                ldmx4(al[mi], aH + PART_SZ + (u32)(mi * 16 * ROWB));
            }
            #pragma unroll
            for (int nb = 0; nb < 2; nb++) {
                ldmx4(bh[nb], bH + (u32)(nb * 16 * ROWB));
                ldmx4(bl[nb], bH + PART_SZ + (u32)(nb * 16 * ROWB));
            }
            #pragma unroll
            for (int mi = 0; mi < 4; mi++)
                #pragma unroll
                for (int ni = 0; ni < 4; ni++) {
                    const u32* bhp = &bh[ni >> 1][(ni & 1) * 2];
                    const u32* blp = &bl[ni >> 1][(ni & 1) * 2];
                    mma_bf16(acc[mi][ni], ah[mi], bhp);
                    mma_bf16(acc[mi][ni], ah[mi], blp);
                    mma_bf16(acc[mi][ni], al[mi], bhp);
                }
        }
        __syncthreads();
        if (c + 2 < NCH) {
            issue_chunk(bufs + (u32)(c & 1) * BUF_SZ, Ah, Al, Bh, Bl, m0, n0, c + 2, tid);
            asm volatile("cp.async.commit_group;" ::: "memory");
        }
    }

    const int g = lane >> 2, tq = lane & 3;
    #pragma unroll
    for (int mi = 0; mi < 4; mi++) {
        #pragma unroll
        for (int ni = 0; ni < 4; ni++) {
            int row = m0 + wm * 64 + mi * 16 + g;
            int nl  = wn * 32 + ni * 8 + 2 * tq;
            float b0v = bs[nl], b1v = bs[nl + 1];
            float2 v0 = make_float2(acc[mi][ni][0] + b0v, acc[mi][ni][1] + b1v);
            float2 v1 = make_float2(acc[mi][ni][2] + b0v, acc[mi][ni][3] + b1v);
            *(float2*)&C[(size_t)row * Nld + n0 + nl]       = v0;
            *(float2*)&C[(size_t)(row + 8) * Nld + n0 + nl] = v1;
        }
    }
}

// ---------------- HMMA flash attention ----------------
// CTA = (qtile 128, h, t). 8 warps x 16 q-rows. KV chunks of 128, online softmax.
// 3-term emulated fp32 for both Q*K^T and P*V. V stored transposed in smem so the
// proven non-trans laneB ldmatrix pattern applies. Output written as bf16 hi/lo
// directly into g_Ah/g_Al (feeds hgemm2, no split pass needed).
#define QROW 144          // 64 bf16 (128B) + 16B pad
#define VROW 272          // 128 bf16 (256B) + 16B pad
#define AQ_H 0
#define AQ_L 18432
#define AK_H 36864
#define AK_L 55296
#define AV_H 73728
#define AV_L 91136
#define ATTN_SMEM 108544

__global__ __launch_bounds__(256, 1)
void attn_mma()
{
    extern __shared__ char smem[];
    const u32 sb = smem_u32(smem);
    const int tid  = threadIdx.x;
    const int lane = tid & 31, wid = tid >> 5;
    const int g = lane >> 2, tq = lane & 3;
    const int qt = blockIdx.x, h = blockIdx.y, t = blockIdx.z;

    const u32 laneA  = (u32)((lane & 15) * QROW + (lane >> 4) * 16);
    const u32 laneBK = (u32)(((((lane >> 4) << 3) + (lane & 7)) * QROW) + ((lane >> 3) & 1) * 16);
    const u32 laneBV = (u32)(((((lane >> 4) << 3) + (lane & 7)) * VROW) + ((lane >> 3) & 1) * 16);

    // ---- load Q tile (128 x 64), scale by 1/8, split to bf16 hi/lo ----
    {
        const float* qsrc = g_qkv + (size_t)(t * BB + qt * 128) * D3 + h * HDIM;
        #pragma unroll
        for (int it = 0; it < 8; it++) {
            int slot = it * 256 + tid;
            int row = slot >> 4, c4 = slot & 15;
            float4 v = *(const float4*)(qsrc + (size_t)row * D3 + c4 * 4);
            v.x *= 0.125f; v.y *= 0.125f; v.z *= 0.125f; v.w *= 0.125f;
            __nv_bfloat162 h01 = __floats2bfloat162_rn(v.x, v.y);
            __nv_bfloat162 h23 = __floats2bfloat162_rn(v.z, v.w);
            __nv_bfloat162 l01 = __floats2bfloat162_rn(v.x - __low2float(h01), v.y - __high2float(h01));
            __nv_bfloat162 l23 = __floats2bfloat162_rn(v.z - __low2float(h23), v.w - __high2float(h23));
            u32 off = (u32)(row * QROW + c4 * 8);
            *(__nv_bfloat162*)(smem + AQ_H + off)     = h01;
            *(__nv_bfloat162*)(smem + AQ_H + off + 4) = h23;
            *(__nv_bfloat162*)(smem + AQ_L + off)     = l01;
            *(__nv_bfloat162*)(smem + AQ_L + off + 4) = l23;
        }
    }

    float cO[8][4];
    #pragma unroll
    for (int j = 0; j < 8; j++)
        #pragma unroll
        for (int i = 0; i < 4; i++) cO[j][i] = 0.f;
    float m_g = -3.402823466e38f, m_g8 = -3.402823466e38f;
    float l_g = 0.f, l_g8 = 0.f;

    #pragma unroll 1
    for (int c = 0; c < 4; c++) {
        __syncthreads();    // previous chunk's compute done before overwrite (covers Q store too)

        // ---- load K chunk (128 keys x 64), split hi/lo ----
        {
            const float* ksrc = g_qkv + (size_t)(t * BB + c * 128) * D3 + DD + h * HDIM;
            #pragma unroll
            for (int it = 0; it < 8; it++) {
                int slot = it * 256 + tid;
                int row = slot >> 4, c4 = slot & 15;
                float4 v = *(const float4*)(ksrc + (size_t)row * D3 + c4 * 4);
                __nv_bfloat162 h01 = __floats2bfloat162_rn(v.x, v.y);
                __nv_bfloat162 h23 = __floats2bfloat162_rn(v.z, v.w);
                __nv_bfloat162 l01 = __floats2bfloat162_rn(v.x - __low2float(h01), v.y - __high2float(h01));
                __nv_bfloat162 l23 = __floats2bfloat162_rn(v.z - __low2float(h23), v.w - __high2float(h23));
                u32 off = (u32)(row * QROW + c4 * 8);
                *(__nv_bfloat162*)(smem + AK_H + off)     = h01;
                *(__nv_bfloat162*)(smem + AK_H + off + 4) = h23;
                *(__nv_bfloat162*)(smem + AK_L + off)     = l01;
                *(__nv_bfloat162*)(smem + AK_L + off + 4) = l23;
            }
        }
        // ---- load V chunk transposed: Vt[d][key], split hi/lo ----
        {
            const float* vsrc = g_qkv + (size_t)(t * BB + c * 128) * D3 + 2 * DD + h * HDIM;
            #pragma unroll
            for (int it = 0; it < 8; it++) {
                int slot = it * 256 + tid;
                int key = slot & 127, d4 = slot >> 7;
                float4 v = *(const float4*)(vsrc + (size_t)key * D3 + d4 * 4);
                float f[4] = {v.x, v.y, v.z, v.w};
                #pragma unroll
                for (int dd = 0; dd < 4; dd++) {
                    __nv_bfloat16 hb = __float2bfloat16_rn(f[dd]);
                    __nv_bfloat16 lb = __float2bfloat16_rn(f[dd] - __bfloat162float(hb));
                    u32 off = (u32)((d4 * 4 + dd) * VROW + key * 2);
                    *(__nv_bfloat16*)(smem + AV_H + off) = hb;
                    *(__nv_bfloat16*)(smem + AV_L + off) = lb;
                }
            }
        }
        __syncthreads();

        // ---- S = Q K^T (16 q-rows per warp x 128 keys), 3-term ----
        float cS[16][4];
        #pragma unroll
        for (int j = 0; j < 16; j++)
            #pragma unroll
            for (int i = 0; i < 4; i++) cS[j][i] = 0.f;

        const u32 qbh = sb + AQ_H + (u32)(wid * 16 * QROW) + laneA;
        const u32 qbl = sb + AQ_L + (u32)(wid * 16 * QROW) + laneA;
        #pragma unroll
        for (int kk = 0; kk < 4; kk++) {
            u32 ah[4], al[4];
            ldmx4(ah, qbh + (u32)(kk * 32));
            ldmx4(al, qbl + (u32)(kk * 32));
            #pragma unroll
            for (int p = 0; p < 8; p++) {
                u32 bh[4], bl[4];
                u32 kb = (u32)(p * 16 * QROW + kk * 32);
                ldmx4(bh, sb + AK_H + kb + laneBK);
                ldmx4(bl, sb + AK_L + kb + laneBK);
                mma_bf16(cS[2 * p],     ah, bh);     mma_bf16(cS[2 * p],     ah, bl);
                mma_bf16(cS[2 * p],     al, bh);
                mma_bf16(cS[2 * p + 1], ah, bh + 2); mma_bf16(cS[2 * p + 1], ah, bl + 2);
                mma_bf16(cS[2 * p + 1], al, bh + 2);
            }
        }

        // ---- online softmax (rows g and g+8 of this thread) ----
        float mg = -3.402823466e38f, mg8 = -3.402823466e38f;
        #pragma unroll
        for (int j = 0; j < 16; j++) {
            mg  = fmaxf(mg,  fmaxf(cS[j][0], cS[j][1]));
            mg8 = fmaxf(mg8, fmaxf(cS[j][2], cS[j][3]));
        }
        mg  = fmaxf(mg,  __shfl_xor_sync(0xffffffffu, mg, 1));
        mg  = fmaxf(mg,  __shfl_xor_sync(0xffffffffu, mg, 2));
        mg8 = fmaxf(mg8, __shfl_xor_sync(0xffffffffu, mg8, 1));
        mg8 = fmaxf(mg8, __shfl_xor_sync(0xffffffffu, mg8, 2));

        float mn_g  = fmaxf(m_g, mg);
        float mn_g8 = fmaxf(m_g8, mg8);
        float cr_g  = __expf(m_g - mn_g);     // first chunk: exp(-inf)=0
        float cr_g8 = __expf(m_g8 - mn_g8);
        m_g = mn_g; m_g8 = mn_g8;
        l_g *= cr_g; l_g8 *= cr_g8;
        #pragma unroll
        for (int j = 0; j < 8; j++) {
            cO[j][0] *= cr_g;  cO[j][1] *= cr_g;
            cO[j][2] *= cr_g8; cO[j][3] *= cr_g8;
        }
        #pragma unroll
        for (int j = 0; j < 16; j++) {
            cS[j][0] = __expf(cS[j][0] - m_g);
            cS[j][1] = __expf(cS[j][1] - m_g);
            cS[j][2] = __expf(cS[j][2] - m_g8);
            cS[j][3] = __expf(cS[j][3] - m_g8);
            l_g  += cS[j][0] + cS[j][1];
            l_g8 += cS[j][2] + cS[j][3];
        }

        // ---- O += P V (3-term, P hi/lo built in fragment registers) ----
        #pragma unroll
        for (int kk = 0; kk < 8; kk++) {
            float* p0 = cS[2 * kk];      // keys 16kk..+7
            float* p1 = cS[2 * kk + 1];  // keys 16kk+8..+15
            __nv_bfloat16 h00 = __float2bfloat16_rn(p0[0]), h01b = __float2bfloat16_rn(p0[1]);
            __nv_bfloat16 h02 = __float2bfloat16_rn(p0[2]), h03 = __float2bfloat16_rn(p0[3]);
            __nv_bfloat16 h10 = __float2bfloat16_rn(p1[0]), h11 = __float2bfloat16_rn(p1[1]);
            __nv_bfloat16 h12 = __float2bfloat16_rn(p1[2]), h13 = __float2bfloat16_rn(p1[3]);
            u32 pa[4], pl[4];
            pa[0] = b2u(h00, h01b); pa[1] = b2u(h02, h03);
            pa[2] = b2u(h10, h11);  pa[3] = b2u(h12, h13);
            pl[0] = b2u(__float2bfloat16_rn(p0[0] - __bfloat162float(h00)),
                        __float2bfloat16_rn(p0[1] - __bfloat162float(h01b)));
            pl[1] = b2u(__float2bfloat16_rn(p0[2] - __bfloat162float(h02)),
                        __float2bfloat16_rn(p0[3] - __bfloat162float(h03)));
            pl[2] = b2u(__float2bfloat16_rn(p1[0] - __bfloat162float(h10)),
                        __float2bfloat16_rn(p1[1] - __bfloat162float(h11)));
            pl[3] = b2u(__float2bfloat16_rn(p1[2] - __bfloat162float(h12)),
                        __float2bfloat16_rn(p1[3] - __bfloat162float(h13)));
            #pragma unroll
            for (int p = 0; p < 4; p++) {    // d-tile pairs (8 n8 tiles of 64 d)
                u32 vh[4], vl[4];
                u32 vb = (u32)(p * 16 * VROW + kk * 32);
                ldmx4(vh, sb + AV_H + vb + laneBV);
                ldmx4(vl, sb + AV_L + vb + laneBV);
                mma_bf16(cO[2 * p],     pa, vh);     mma_bf16(cO[2 * p],     pa, vl);
                mma_bf16(cO[2 * p],     pl, vh);
                mma_bf16(cO[2 * p + 1], pa, vh + 2); mma_bf16(cO[2 * p + 1], pa, vl + 2);
                mma_bf16(cO[2 * p + 1], pl, vh + 2);
            }
        }
    }

    // ---- finalize: normalize, write ctx as bf16 hi/lo (feeds hgemm2) ----
    l_g  += __shfl_xor_sync(0xffffffffu, l_g, 1);
    l_g  += __shfl_xor_sync(0xffffffffu, l_g, 2);
    l_g8 += __shfl_xor_sync(0xffffffffu, l_g8, 1);
    l_g8 += __shfl_xor_sync(0xffffffffu, l_g8, 2);
    float il_g = 1.f / l_g, il_g8 = 1.f / l_g8;

    const int r0 = t * BB + qt * 128 + wid * 16 + g;
    #pragma unroll
    for (int j = 0; j < 8; j++) {
        int gc = h * HDIM + j * 8 + 2 * tq;
        float o00 = cO[j][0] * il_g,  o01 = cO[j][1] * il_g;
        float o10 = cO[j][2] * il_g8, o11 = cO[j][3] * il_g8;
        __nv_bfloat16 a0 = __float2bfloat16_rn(o00), a1 = __float2bfloat16_rn(o01);
        __nv_bfloat16 b0 = __float2bfloat16_rn(o10), b1 = __float2bfloat16_rn(o11);
        *(u32*)&g_Ah[(size_t)r0 * DD + gc] = b2u(a0, a1);
        *(u32*)&g_Al[(size_t)r0 * DD + gc] =
            b2u(__float2bfloat16_rn(o00 - __bfloat162float(a0)),
                __float2bfloat16_rn(o01 - __bfloat162float(a1)));
        *(u32*)&g_Ah[(size_t)(r0 + 8) * DD + gc] = b2u(b0, b1);
        *(u32*)&g_Al[(size_t)(r0 + 8) * DD + gc] =
            b2u(__float2bfloat16_rn(o10 - __bfloat162float(b0)),
                __float2bfloat16_rn(o11 - __bfloat162float(b1)));
    }
}

// ---------------- mean of normalized rows per t ----------------
__global__ __launch_bounds__(256)
void mean_kernel()
{
    const int t    = blockIdx.x;
    const int warp = threadIdx.x >> 5;
    const int lane = threadIdx.x & 31;

    float macc[24];
    #pragma unroll
    for (int k = 0; k < 24; k++) macc[k] = 0.f;

    for (int b = warp; b < BB; b += 8) {
        const float* row = &g_out[(size_t)(t * BB + b) * DD];
        float x[24];
        float ss = 0.f;
        #pragma unroll
        for (int k = 0; k < 24; k++) {
            x[k] = row[lane + 32 * k];
            ss += x[k] * x[k];
        }
        #pragma unroll
        for (int o = 16; o; o >>= 1) ss += __shfl_xor_sync(0xffffffffu, ss, o);
        float r = 1.f / fmaxf(sqrtf(ss), 1e-8f);
        #pragma unroll
        for (int k = 0; k < 24; k++) macc[k] += x[k] * r;
    }

    __shared__ float sm[8][DD];
    #pragma unroll
    for (int k = 0; k < 24; k++) sm[warp][lane + 32 * k] = macc[k];
    __syncthreads();

    for (int d = threadIdx.x; d < DD; d += 256) {
        float s = 0.f;
        #pragma unroll
        for (int w = 0; w < 8; w++) s += sm[w][d];
        g_mean[t * DD + d] = s * (1.f / (float)BB);
    }
}

// ---------------- adjacency: one warp per (t,b) row ----------------
__global__ __launch_bounds__(256)
void adj_kernel(float* __restrict__ adj)
{
    const int row  = blockIdx.x * 8 + (threadIdx.x >> 5);
    const int lane = threadIdx.x & 31;
    const int t    = row >> 9;

    const float* __restrict__ x = &g_out[(size_t)row * DD];
    const float* __restrict__ mv = &g_mean[t * DD];

    float dot = 0.f, ss = 0.f;
    #pragma unroll
    for (int k = 0; k < 24; k++) {
        float v = x[lane + 32 * k];
        dot += v * mv[lane + 32 * k];
        ss  += v * v;
    }
    #pragma unroll
    for (int o = 16; o; o >>= 1) {
        dot += __shfl_xor_sync(0xffffffffu, dot, o);
        ss  += __shfl_xor_sync(0xffffffffu, ss, o);
    }
    if (lane == 0)
        adj[row] = dot / fmaxf(sqrtf(ss), 1e-8f);
}

// ---------------- launch ----------------
static const float* find_by_count(void* const* d_in, const int* in_sizes,
                                  int n_in, int count)
{
    for (int i = 0; i < n_in; i++)
        if (in_sizes[i] == count) return (const float*)d_in[i];
    return nullptr;
}

extern "C" void kernel_launch(void* const* d_in, const int* in_sizes, int n_in,
                              void* d_out, int out_size)
{
    const float* node  = find_by_count(d_in, in_sizes, n_in, TB * DD);
    const float* w_in  = find_by_count(d_in, in_sizes, n_in, D3 * DD);
    const float* b_in  = find_by_count(d_in, in_sizes, n_in, D3);
    const float* w_out = find_by_count(d_in, in_sizes, n_in, DD * DD);
    const float* b_out = find_by_count(d_in, in_sizes, n_in, DD);
    float* adj = (float*)d_out;

    float *qkv_p, *out_p;
    __nv_bfloat16 *ah_p, *al_p, *wh_p, *wl_p;
    cudaGetSymbolAddress((void**)&qkv_p, g_qkv);
    cudaGetSymbolAddress((void**)&out_p, g_out);
    cudaGetSymbolAddress((void**)&ah_p, g_Ah);
    cudaGetSymbolAddress((void**)&al_p, g_Al);
    cudaGetSymbolAddress((void**)&wh_p, g_Wh);
    cudaGetSymbolAddress((void**)&wl_p, g_Wl);

    cudaFuncSetAttribute(hgemm, cudaFuncAttributeMaxDynamicSharedMemorySize, GEMM_SMEM);
    cudaFuncSetAttribute(attn_mma, cudaFuncAttributeMaxDynamicSharedMemorySize, ATTN_SMEM);

    // 1) split node_embs + in_proj weights to bf16 hi/lo
    split4<<<(TB * DD / 4 + 255) / 256, 256>>>(node, ah_p, al_p, TB * DD / 4);
    split4<<<(D3 * DD / 4 + 255) / 256, 256>>>(w_in, wh_p, wl_p, D3 * DD / 4);
    // 2) QKV projection (HMMA, emulated fp32)
    hgemm<<<dim3(D3 / 128, TB / 128), 256, GEMM_SMEM>>>(ah_p, al_p, wh_p, wl_p, b_in, qkv_p, D3);
    // 3) flash attention (HMMA); writes ctx as bf16 hi/lo into g_Ah/g_Al
    attn_mma<<<dim3(4, HH, TT), 256, ATTN_SMEM>>>();
    // 4) split out_proj weights (after hgemm1 released Wh/Wl)
    split4<<<(DD * DD / 4 + 255) / 256, 256>>>(w_out, wh_p, wl_p, DD * DD / 4);
    // 5) out projection
    hgemm<<<dim3(DD / 128, TB / 128), 256, GEMM_SMEM>>>(ah_p, al_p, wh_p, wl_p, b_out, out_p, DD);
    // 6) per-t mean of normalized rows
    mean_kernel<<<TT, 256>>>();
    // 7) adjacency output
    adj_kernel<<<TB / 8, 256>>>(adj);
}